// round 11
// baseline (speedup 1.0000x reference)
#include <cuda_runtime.h>
#include <cstdint>

#define HID 128
#define NMAX 50000
#define EMAX 600000

#define PK 132            // A smem row stride (floats)
#define PN 136            // W smem row stride (floats)
#define SA_LO (64 * PK)
#define SW_HI (2 * 64 * PK)
#define SW_LO (2 * 64 * PK + 128 * PN)
#define SM_FLOATS (2 * 64 * PK + 2 * 128 * PN)   // 51712 floats = 202 KB

// Scratch (static __device__ — no allocations allowed)
__device__ float g_dinv[NMAX];
__device__ float g_hws[(size_t)NMAX * HID];
__device__ float g_h  [(size_t)NMAX * HID];
__device__ int   g_deg[NMAX];
__device__ int   g_rowptr[NMAX + 1];
__device__ int   g_cursor[NMAX];
__device__ int   g_col[EMAX];
__device__ int   g_bsum[128];
__device__ int   g_mode;                      // 1 => edge_index int64, 0 => int32
__device__ float g_Wimg[3][2][128 * PN];      // W split hi/lo, k-major padded

// ---------------------------------------------------------------------------
__device__ __forceinline__ float tf32_hi(float x) {
    uint32_t r; asm("cvt.rna.tf32.f32 %0, %1;" : "=r"(r) : "f"(x));
    return __uint_as_float(r);
}
__device__ __forceinline__ void mma8(float* c, const uint32_t* a, const uint32_t* b) {
    asm volatile(
        "mma.sync.aligned.m16n8k8.row.col.f32.tf32.tf32.f32 "
        "{%0,%1,%2,%3}, {%4,%5,%6,%7}, {%8,%9}, {%0,%1,%2,%3};"
        : "+f"(c[0]), "+f"(c[1]), "+f"(c[2]), "+f"(c[3])
        : "r"(a[0]), "r"(a[1]), "r"(a[2]), "r"(a[3]), "r"(b[0]), "r"(b[1]));
}

// ---------------------------------------------------------------------------
// Preamble: dtype detect + CSR build (unchanged from R6)
__global__ void k_detect_zero(const void* __restrict__ ei, int n) {
    int i = blockIdx.x * blockDim.x + threadIdx.x;
    if (i < n) g_deg[i] = 0;
    if (blockIdx.x == 0 && threadIdx.x < 32) {
        const long long* p = (const long long*)ei;
        int ok = 1;
        for (int k = threadIdx.x; k < 128; k += 32) {
            long long v = p[k];
            if (v < 0 || v >= (long long)n) ok = 0;
        }
        ok = __all_sync(0xffffffffu, ok);
        if (threadIdx.x == 0) g_mode = ok;
    }
}
__global__ void k_hist(const void* __restrict__ ei, int E) {
    int e = blockIdx.x * blockDim.x + threadIdx.x;
    if (e >= E) return;
    int d;
    if (g_mode) d = (int)((const long long*)ei)[(size_t)E + e];
    else        d = ((const int*)ei)[(size_t)E + e];
    atomicAdd(&g_deg[d], 1);
}
__global__ void k_scan1(int n) {
    __shared__ int s[1024];
    int i = blockIdx.x * 1024 + threadIdx.x;
    int v = (i < n) ? g_deg[i] : 0;
    s[threadIdx.x] = v;
    __syncthreads();
    int acc = v;
    #pragma unroll
    for (int off = 1; off < 1024; off <<= 1) {
        int t = (threadIdx.x >= off) ? s[threadIdx.x - off] : 0;
        __syncthreads();
        acc += t;
        s[threadIdx.x] = acc;
        __syncthreads();
    }
    if (i < n) g_rowptr[i] = acc - v;
    if (threadIdx.x == 1023) g_bsum[blockIdx.x] = acc;
}
__global__ void k_scan3(int n, int E, int nb) {
    __shared__ int s[129];
    if (threadIdx.x == 0) {
        int acc = 0;
        for (int k = 0; k < nb; k++) { s[k] = acc; acc += g_bsum[k]; }
    }
    __syncthreads();
    int i = blockIdx.x * blockDim.x + threadIdx.x;
    if (i < n) {
        int r = g_rowptr[i] + s[i >> 10];
        g_rowptr[i] = r;
        g_cursor[i] = r;
        g_dinv[i] = rsqrtf((float)(g_deg[i] + 1));
    }
    if (i == 0) g_rowptr[n] = E;
}
__global__ void k_fill(const void* __restrict__ ei, int E) {
    int e = blockIdx.x * blockDim.x + threadIdx.x;
    if (e >= E) return;
    int s, d;
    if (g_mode) {
        const long long* p = (const long long*)ei;
        s = (int)p[e]; d = (int)p[(size_t)E + e];
    } else {
        const int* p = (const int*)ei;
        s = p[e]; d = p[(size_t)E + e];
    }
    int pos = atomicAdd(&g_cursor[d], 1);
    g_col[pos] = s;
}

// ---------------------------------------------------------------------------
// Pre-split W into tf32 hi/lo, k-major padded image (stride PN), once.
__global__ void k_prepB(const float* __restrict__ W0, const float* __restrict__ W1,
                        const float* __restrict__ W2) {
    const float* W = (blockIdx.y == 0) ? W0 : (blockIdx.y == 1) ? W1 : W2;
    int idx = blockIdx.x * 256 + threadIdx.x;   // k*128 + nn
    int k = idx >> 7, nn = idx & 127;
    float v = W[idx];
    float hi = tf32_hi(v);
    g_Wimg[blockIdx.y][0][k * PN + nn] = hi;
    g_Wimg[blockIdx.y][1][k * PN + nn] = tf32_hi(v - hi);
}

// ---------------------------------------------------------------------------
// Tensor-core GEMM (legacy mma.sync tf32, 3x split):
// hws = (h @ W) * dinv[row].  Block: 256 thr, M=64 x N=128; warp = 32x32.
__global__ void __launch_bounds__(256, 1)
k_gemm_mma(const float* __restrict__ h, int layer, int n) {
    extern __shared__ float sm[];
    float* sAhi = sm;
    float* sAlo = sm + SA_LO;
    float* sWhi = sm + SW_HI;
    float* sWlo = sm + SW_LO;
    int tid = threadIdx.x, lane = tid & 31, wid = tid >> 5;
    int row0 = blockIdx.x * 64;

    // stage W (prebuilt split images, linear float4 copy)
    {
        const float4* wh = (const float4*)g_Wimg[layer][0];
        const float4* wl = (const float4*)g_Wimg[layer][1];
        float4* dh = (float4*)sWhi;
        float4* dl = (float4*)sWlo;
        for (int i = tid; i < 128 * PN / 4; i += 256) { dh[i] = wh[i]; dl[i] = wl[i]; }
    }
    // stage A split
    {
        const float4* h4 = (const float4*)h;
        for (int i = tid; i < 64 * 32; i += 256) {
            int r = i >> 5, k4 = i & 31;
            int row = row0 + r;
            float4 v = (row < n) ? h4[(size_t)row * 32 + k4]
                                 : make_float4(0.f, 0.f, 0.f, 0.f);
            float hx = tf32_hi(v.x), hy = tf32_hi(v.y), hz = tf32_hi(v.z), hw = tf32_hi(v.w);
            *(float4*)&sAhi[r * PK + 4 * k4] = make_float4(hx, hy, hz, hw);
            *(float4*)&sAlo[r * PK + 4 * k4] =
                make_float4(tf32_hi(v.x - hx), tf32_hi(v.y - hy),
                            tf32_hi(v.z - hz), tf32_hi(v.w - hw));
        }
    }
    __syncthreads();

    int g  = lane >> 2, tg = lane & 3;
    int m0 = (wid >> 2) * 32, n0 = (wid & 3) * 32;

    float acc[2][4][4];
    #pragma unroll
    for (int mf = 0; mf < 2; mf++)
        #pragma unroll
        for (int nf = 0; nf < 4; nf++)
            #pragma unroll
            for (int j = 0; j < 4; j++) acc[mf][nf][j] = 0.f;

    #pragma unroll 4
    for (int ks = 0; ks < 16; ks++) {
        int k0 = ks * 8;
        uint32_t ah[2][4], al[2][4];
        #pragma unroll
        for (int mf = 0; mf < 2; mf++) {
            int rb = m0 + mf * 16;
            ah[mf][0] = __float_as_uint(sAhi[(rb + g) * PK + k0 + tg]);
            ah[mf][1] = __float_as_uint(sAhi[(rb + g + 8) * PK + k0 + tg]);
            ah[mf][2] = __float_as_uint(sAhi[(rb + g) * PK + k0 + tg + 4]);
            ah[mf][3] = __float_as_uint(sAhi[(rb + g + 8) * PK + k0 + tg + 4]);
            al[mf][0] = __float_as_uint(sAlo[(rb + g) * PK + k0 + tg]);
            al[mf][1] = __float_as_uint(sAlo[(rb + g + 8) * PK + k0 + tg]);
            al[mf][2] = __float_as_uint(sAlo[(rb + g) * PK + k0 + tg + 4]);
            al[mf][3] = __float_as_uint(sAlo[(rb + g + 8) * PK + k0 + tg + 4]);
        }
        #pragma unroll
        for (int nf = 0; nf < 4; nf++) {
            int cb = n0 + nf * 8 + g;
            uint32_t bh[2], bl[2];
            bh[0] = __float_as_uint(sWhi[(k0 + tg) * PN + cb]);
            bh[1] = __float_as_uint(sWhi[(k0 + tg + 4) * PN + cb]);
            bl[0] = __float_as_uint(sWlo[(k0 + tg) * PN + cb]);
            bl[1] = __float_as_uint(sWlo[(k0 + tg + 4) * PN + cb]);
            #pragma unroll
            for (int mf = 0; mf < 2; mf++) {
                mma8(acc[mf][nf], ah[mf], bh);
                mma8(acc[mf][nf], al[mf], bh);
                mma8(acc[mf][nf], ah[mf], bl);
            }
        }
    }

    // epilogue: c0,c1 -> (row g, cols tg*2,tg*2+1); c2,c3 -> row g+8
    #pragma unroll
    for (int mf = 0; mf < 2; mf++) {
        #pragma unroll
        for (int half = 0; half < 2; half++) {
            int row = row0 + m0 + mf * 16 + g + half * 8;
            if (row < n) {
                float dv = g_dinv[row];
                #pragma unroll
                for (int nf = 0; nf < 4; nf++) {
                    int col = n0 + nf * 8 + tg * 2;
                    float2 o = make_float2(acc[mf][nf][half * 2] * dv,
                                           acc[mf][nf][half * 2 + 1] * dv);
                    *(float2*)&g_hws[(size_t)row * HID + col] = o;
                }
            }
        }
    }
}

// ---------------------------------------------------------------------------
// Gather-aggregate + finalize (unchanged): one warp per dst node, 4 loads in flight
__global__ void k_agg(const float* __restrict__ b, float* __restrict__ out, int n) {
    int warp = (blockIdx.x * blockDim.x + threadIdx.x) >> 5;
    int lane = threadIdx.x & 31;
    if (warp >= n) return;
    int beg = g_rowptr[warp], end = g_rowptr[warp + 1];

    const float4* hws4 = (const float4*)g_hws;
    float4 sum = hws4[(size_t)warp * 32 + lane];   // self loop

    for (int base = beg; base < end; base += 32) {
        int m = end - base; if (m > 32) m = 32;
        int idx = (lane < m) ? g_col[base + lane] : 0;
        int k = 0;
        for (; k + 4 <= m; k += 4) {
            int s0 = __shfl_sync(0xffffffffu, idx, k);
            int s1 = __shfl_sync(0xffffffffu, idx, k + 1);
            int s2 = __shfl_sync(0xffffffffu, idx, k + 2);
            int s3 = __shfl_sync(0xffffffffu, idx, k + 3);
            float4 v0 = hws4[(size_t)s0 * 32 + lane];
            float4 v1 = hws4[(size_t)s1 * 32 + lane];
            float4 v2 = hws4[(size_t)s2 * 32 + lane];
            float4 v3 = hws4[(size_t)s3 * 32 + lane];
            sum.x += (v0.x + v1.x) + (v2.x + v3.x);
            sum.y += (v0.y + v1.y) + (v2.y + v3.y);
            sum.z += (v0.z + v1.z) + (v2.z + v3.z);
            sum.w += (v0.w + v1.w) + (v2.w + v3.w);
        }
        for (; k < m; k++) {
            int s = __shfl_sync(0xffffffffu, idx, k);
            float4 v = hws4[(size_t)s * 32 + lane];
            sum.x += v.x; sum.y += v.y; sum.z += v.z; sum.w += v.w;
        }
    }

    float dv = g_dinv[warp];
    float4 bb = ((const float4*)b)[lane];
    float4 o;
    o.x = fmaxf(fmaf(sum.x, dv, bb.x), 0.f);
    o.y = fmaxf(fmaf(sum.y, dv, bb.y), 0.f);
    o.z = fmaxf(fmaf(sum.z, dv, bb.z), 0.f);
    o.w = fmaxf(fmaf(sum.w, dv, bb.w), 0.f);
    ((float4*)out)[(size_t)warp * 32 + lane] = o;
}

// ---------------------------------------------------------------------------
extern "C" void kernel_launch(void* const* d_in, const int* in_sizes, int n_in,
                              void* d_out, int out_size) {
    const float* x  = (const float*)d_in[0];
    const void*  ei = d_in[1];
    const float* Ws[3] = {(const float*)d_in[2], (const float*)d_in[4], (const float*)d_in[6]};
    const float* bs[3] = {(const float*)d_in[3], (const float*)d_in[5], (const float*)d_in[7]};
    int n = in_sizes[0] / HID;
    int E = in_sizes[1] / 2;

    const int smem = SM_FLOATS * 4;   // 202 KB
    cudaFuncSetAttribute(k_gemm_mma, cudaFuncAttributeMaxDynamicSharedMemorySize, smem);

    float* gh = nullptr;
    cudaGetSymbolAddress((void**)&gh, g_h);

    const int tb = 256;
    int nb_scan = (n + 1023) / 1024;

    k_prepB<<<dim3(64, 3), 256>>>(Ws[0], Ws[1], Ws[2]);
    k_detect_zero<<<(n + tb - 1) / tb, tb>>>(ei, n);
    k_hist<<<(E + tb - 1) / tb, tb>>>(ei, E);
    k_scan1<<<nb_scan, 1024>>>(n);
    k_scan3<<<(n + tb - 1) / tb, tb>>>(n, E, nb_scan);
    k_fill<<<(E + tb - 1) / tb, tb>>>(ei, E);

    const float* hin = x;
    for (int l = 0; l < 3; l++) {
        k_gemm_mma<<<(n + 63) / 64, 256, smem>>>(hin, l, n);
        float* out = (l == 2) ? (float*)d_out : gh;
        k_agg<<<(n * 32 + tb - 1) / tb, tb>>>(bs[l], out, n);
        hin = gh;
    }
}

// round 12
// speedup vs baseline: 1.5573x; 1.5573x over previous
#include <cuda_runtime.h>
#include <cuda_bf16.h>
#include <cstdint>

#define HID 128
#define NMAX 50000
#define EMAX 600000

// smem layout for bf16 GEMM (row stride 136 bf16 = 272 bytes)
#define AST 272
#define SA_BYTES (64 * AST)       // 17408
#define SW_BYTES (128 * AST)      // 34816
#define OFF_ALO SA_BYTES
#define OFF_WHI (2 * SA_BYTES)
#define OFF_WLO (2 * SA_BYTES + SW_BYTES)
#define SMEM_TOT (2 * SA_BYTES + 2 * SW_BYTES)   // 104448 B

// Scratch (static __device__ — no allocations allowed)
__device__ float g_dinv[NMAX];
__device__ float g_hws[(size_t)NMAX * HID];
__device__ float g_h  [(size_t)NMAX * HID];
__device__ int   g_deg[NMAX];
__device__ int   g_rowptr[NMAX + 1];
__device__ int   g_cursor[NMAX];
__device__ int   g_col[EMAX];
__device__ int   g_bsum[128];
__device__ int   g_mode;                               // 1 => int64 edges, 0 => int32
__device__ __nv_bfloat16 g_Wimg[3][2][128 * 136];      // W^T split hi/lo, n-major padded

// ---------------------------------------------------------------------------
__device__ __forceinline__ uint32_t pack_bf16(float lo_elem, float hi_elem) {
    uint32_t r;
    asm("cvt.rn.bf16x2.f32 %0, %1, %2;" : "=r"(r) : "f"(hi_elem), "f"(lo_elem));
    return r;
}
__device__ __forceinline__ void mma16(float* c, const uint32_t* a, const uint32_t* b) {
    asm volatile(
        "mma.sync.aligned.m16n8k16.row.col.f32.bf16.bf16.f32 "
        "{%0,%1,%2,%3}, {%4,%5,%6,%7}, {%8,%9}, {%0,%1,%2,%3};"
        : "+f"(c[0]), "+f"(c[1]), "+f"(c[2]), "+f"(c[3])
        : "r"(a[0]), "r"(a[1]), "r"(a[2]), "r"(a[3]), "r"(b[0]), "r"(b[1]));
}

// ---------------------------------------------------------------------------
// Preamble: dtype detect + CSR build (unchanged)
__global__ void k_detect_zero(const void* __restrict__ ei, int n) {
    int i = blockIdx.x * blockDim.x + threadIdx.x;
    if (i < n) g_deg[i] = 0;
    if (blockIdx.x == 0 && threadIdx.x < 32) {
        const long long* p = (const long long*)ei;
        int ok = 1;
        for (int k = threadIdx.x; k < 128; k += 32) {
            long long v = p[k];
            if (v < 0 || v >= (long long)n) ok = 0;
        }
        ok = __all_sync(0xffffffffu, ok);
        if (threadIdx.x == 0) g_mode = ok;
    }
}
__global__ void k_hist(const void* __restrict__ ei, int E) {
    int e = blockIdx.x * blockDim.x + threadIdx.x;
    if (e >= E) return;
    int d;
    if (g_mode) d = (int)((const long long*)ei)[(size_t)E + e];
    else        d = ((const int*)ei)[(size_t)E + e];
    atomicAdd(&g_deg[d], 1);
}
__global__ void k_scan1(int n) {
    __shared__ int s[1024];
    int i = blockIdx.x * 1024 + threadIdx.x;
    int v = (i < n) ? g_deg[i] : 0;
    s[threadIdx.x] = v;
    __syncthreads();
    int acc = v;
    #pragma unroll
    for (int off = 1; off < 1024; off <<= 1) {
        int t = (threadIdx.x >= off) ? s[threadIdx.x - off] : 0;
        __syncthreads();
        acc += t;
        s[threadIdx.x] = acc;
        __syncthreads();
    }
    if (i < n) g_rowptr[i] = acc - v;
    if (threadIdx.x == 1023) g_bsum[blockIdx.x] = acc;
}
__global__ void k_scan3(int n, int E, int nb) {
    __shared__ int s[129];
    if (threadIdx.x == 0) {
        int acc = 0;
        for (int k = 0; k < nb; k++) { s[k] = acc; acc += g_bsum[k]; }
    }
    __syncthreads();
    int i = blockIdx.x * blockDim.x + threadIdx.x;
    if (i < n) {
        int r = g_rowptr[i] + s[i >> 10];
        g_rowptr[i] = r;
        g_cursor[i] = r;
        g_dinv[i] = rsqrtf((float)(g_deg[i] + 1));
    }
    if (i == 0) g_rowptr[n] = E;
}
__global__ void k_fill(const void* __restrict__ ei, int E) {
    int e = blockIdx.x * blockDim.x + threadIdx.x;
    if (e >= E) return;
    int s, d;
    if (g_mode) {
        const long long* p = (const long long*)ei;
        s = (int)p[e]; d = (int)p[(size_t)E + e];
    } else {
        const int* p = (const int*)ei;
        s = p[e]; d = p[(size_t)E + e];
    }
    int pos = atomicAdd(&g_cursor[d], 1);
    g_col[pos] = s;
}

// ---------------------------------------------------------------------------
// Pre-split W into bf16 hi/lo, transposed [n][k] padded image (stride 136), once.
__global__ void k_prepB(const float* __restrict__ W0, const float* __restrict__ W1,
                        const float* __restrict__ W2) {
    const float* W = (blockIdx.y == 0) ? W0 : (blockIdx.y == 1) ? W1 : W2;
    int idx = blockIdx.x * 256 + threadIdx.x;   // k*128 + nn
    int k = idx >> 7, nn = idx & 127;
    float v = W[idx];
    __nv_bfloat16 hi = __float2bfloat16(v);
    __nv_bfloat16 lo = __float2bfloat16(v - __bfloat162float(hi));
    g_Wimg[blockIdx.y][0][nn * 136 + k] = hi;
    g_Wimg[blockIdx.y][1][nn * 136 + k] = lo;
}

// ---------------------------------------------------------------------------
// Tensor-core GEMM (mma.sync bf16 m16n8k16, 3-term compensated):
// hws = (h @ W) * dinv[row].  Block: 256 thr, M=64 x N=128; warp tile 32x32.
__global__ void __launch_bounds__(256, 2)
k_gemm_bf16(const float* __restrict__ h, int layer, int n) {
    extern __shared__ __align__(16) char sm[];
    char* sA  = sm;
    char* sAl = sm + OFF_ALO;
    char* sW  = sm + OFF_WHI;
    char* sWl = sm + OFF_WLO;
    int tid = threadIdx.x, lane = tid & 31, wid = tid >> 5;
    int row0 = blockIdx.x * 64;

    // stage W (prebuilt split images, linear copy)
    {
        const uint4* wh = (const uint4*)g_Wimg[layer][0];
        const uint4* wl = (const uint4*)g_Wimg[layer][1];
        uint4* dh = (uint4*)sW;
        uint4* dl = (uint4*)sWl;
        for (int i = tid; i < SW_BYTES / 16; i += 256) { dh[i] = wh[i]; dl[i] = wl[i]; }
    }
    // stage A, split hi/lo into bf16
    {
        const float4* h4 = (const float4*)h;
        for (int i = tid; i < 64 * 32; i += 256) {
            int r = i >> 5, c = i & 31;
            int row = row0 + r;
            float4 v = (row < n) ? h4[(size_t)row * 32 + c]
                                 : make_float4(0.f, 0.f, 0.f, 0.f);
            float h0 = __bfloat162float(__float2bfloat16(v.x));
            float h1 = __bfloat162float(__float2bfloat16(v.y));
            float h2 = __bfloat162float(__float2bfloat16(v.z));
            float h3 = __bfloat162float(__float2bfloat16(v.w));
            uint2 hi = make_uint2(pack_bf16(h0, h1), pack_bf16(h2, h3));
            uint2 lo = make_uint2(pack_bf16(v.x - h0, v.y - h1),
                                  pack_bf16(v.z - h2, v.w - h3));
            *(uint2*)(sA  + r * AST + c * 8) = hi;
            *(uint2*)(sAl + r * AST + c * 8) = lo;
        }
    }
    __syncthreads();

    int g = lane >> 2, tg = lane & 3;
    int m0 = (wid >> 2) * 32, n0 = (wid & 3) * 32;

    float acc[2][4][4];
    #pragma unroll
    for (int mf = 0; mf < 2; mf++)
        #pragma unroll
        for (int nf = 0; nf < 4; nf++)
            #pragma unroll
            for (int j = 0; j < 4; j++) acc[mf][nf][j] = 0.f;

    #pragma unroll
    for (int ks = 0; ks < 8; ks++) {
        int kb = ks * 32 + tg * 4;           // byte offset of (k0 + tg*2) bf16
        uint32_t ah[2][4], al[2][4], bh[4][2], bl[4][2];
        #pragma unroll
        for (int mf = 0; mf < 2; mf++) {
            int r0b = (m0 + mf * 16 + g) * AST + kb;
            int r1b = r0b + 8 * AST;
            ah[mf][0] = *(uint32_t*)(sA + r0b);
            ah[mf][1] = *(uint32_t*)(sA + r1b);
            ah[mf][2] = *(uint32_t*)(sA + r0b + 16);
            ah[mf][3] = *(uint32_t*)(sA + r1b + 16);
            al[mf][0] = *(uint32_t*)(sAl + r0b);
            al[mf][1] = *(uint32_t*)(sAl + r1b);
            al[mf][2] = *(uint32_t*)(sAl + r0b + 16);
            al[mf][3] = *(uint32_t*)(sAl + r1b + 16);
        }
        #pragma unroll
        for (int nf = 0; nf < 4; nf++) {
            int cb = (n0 + nf * 8 + g) * AST + kb;
            bh[nf][0] = *(uint32_t*)(sW + cb);
            bh[nf][1] = *(uint32_t*)(sW + cb + 16);
            bl[nf][0] = *(uint32_t*)(sWl + cb);
            bl[nf][1] = *(uint32_t*)(sWl + cb + 16);
        }
        // 3 passes of 8 independent MMAs each -> dependent reuse spaced by 8
        #pragma unroll
        for (int nf = 0; nf < 4; nf++)
            #pragma unroll
            for (int mf = 0; mf < 2; mf++)
                mma16(acc[mf][nf], ah[mf], bh[nf]);
        #pragma unroll
        for (int nf = 0; nf < 4; nf++)
            #pragma unroll
            for (int mf = 0; mf < 2; mf++)
                mma16(acc[mf][nf], al[mf], bh[nf]);
        #pragma unroll
        for (int nf = 0; nf < 4; nf++)
            #pragma unroll
            for (int mf = 0; mf < 2; mf++)
                mma16(acc[mf][nf], ah[mf], bl[nf]);
    }

    // epilogue: c0,c1 -> (row g, cols tg*2,+1); c2,c3 -> row g+8
    #pragma unroll
    for (int mf = 0; mf < 2; mf++) {
        #pragma unroll
        for (int half = 0; half < 2; half++) {
            int row = row0 + m0 + mf * 16 + g + half * 8;
            if (row < n) {
                float dv = g_dinv[row];
                #pragma unroll
                for (int nf = 0; nf < 4; nf++) {
                    int col = n0 + nf * 8 + tg * 2;
                    float2 o = make_float2(acc[mf][nf][half * 2] * dv,
                                           acc[mf][nf][half * 2 + 1] * dv);
                    *(float2*)&g_hws[(size_t)row * HID + col] = o;
                }
            }
        }
    }
}

// ---------------------------------------------------------------------------
// Gather-aggregate + finalize (unchanged): one warp per dst node, 4 loads in flight
__global__ void k_agg(const float* __restrict__ b, float* __restrict__ out, int n) {
    int warp = (blockIdx.x * blockDim.x + threadIdx.x) >> 5;
    int lane = threadIdx.x & 31;
    if (warp >= n) return;
    int beg = g_rowptr[warp], end = g_rowptr[warp + 1];

    const float4* hws4 = (const float4*)g_hws;
    float4 sum = hws4[(size_t)warp * 32 + lane];   // self loop

    for (int base = beg; base < end; base += 32) {
        int m = end - base; if (m > 32) m = 32;
        int idx = (lane < m) ? g_col[base + lane] : 0;
        int k = 0;
        for (; k + 4 <= m; k += 4) {
            int s0 = __shfl_sync(0xffffffffu, idx, k);
            int s1 = __shfl_sync(0xffffffffu, idx, k + 1);
            int s2 = __shfl_sync(0xffffffffu, idx, k + 2);
            int s3 = __shfl_sync(0xffffffffu, idx, k + 3);
            float4 v0 = hws4[(size_t)s0 * 32 + lane];
            float4 v1 = hws4[(size_t)s1 * 32 + lane];
            float4 v2 = hws4[(size_t)s2 * 32 + lane];
            float4 v3 = hws4[(size_t)s3 * 32 + lane];
            sum.x += (v0.x + v1.x) + (v2.x + v3.x);
            sum.y += (v0.y + v1.y) + (v2.y + v3.y);
            sum.z += (v0.z + v1.z) + (v2.z + v3.z);
            sum.w += (v0.w + v1.w) + (v2.w + v3.w);
        }
        for (; k < m; k++) {
            int s = __shfl_sync(0xffffffffu, idx, k);
            float4 v = hws4[(size_t)s * 32 + lane];
            sum.x += v.x; sum.y += v.y; sum.z += v.z; sum.w += v.w;
        }
    }

    float dv = g_dinv[warp];
    float4 bb = ((const float4*)b)[lane];
    float4 o;
    o.x = fmaxf(fmaf(sum.x, dv, bb.x), 0.f);
    o.y = fmaxf(fmaf(sum.y, dv, bb.y), 0.f);
    o.z = fmaxf(fmaf(sum.z, dv, bb.z), 0.f);
    o.w = fmaxf(fmaf(sum.w, dv, bb.w), 0.f);
    ((float4*)out)[(size_t)warp * 32 + lane] = o;
}

// ---------------------------------------------------------------------------
extern "C" void kernel_launch(void* const* d_in, const int* in_sizes, int n_in,
                              void* d_out, int out_size) {
    const float* x  = (const float*)d_in[0];
    const void*  ei = d_in[1];
    const float* Ws[3] = {(const float*)d_in[2], (const float*)d_in[4], (const float*)d_in[6]};
    const float* bs[3] = {(const float*)d_in[3], (const float*)d_in[5], (const float*)d_in[7]};
    int n = in_sizes[0] / HID;
    int E = in_sizes[1] / 2;

    cudaFuncSetAttribute(k_gemm_bf16, cudaFuncAttributeMaxDynamicSharedMemorySize, SMEM_TOT);

    float* gh = nullptr;
    cudaGetSymbolAddress((void**)&gh, g_h);

    const int tb = 256;
    int nb_scan = (n + 1023) / 1024;

    k_prepB<<<dim3(64, 3), 256>>>(Ws[0], Ws[1], Ws[2]);
    k_detect_zero<<<(n + tb - 1) / tb, tb>>>(ei, n);
    k_hist<<<(E + tb - 1) / tb, tb>>>(ei, E);
    k_scan1<<<nb_scan, 1024>>>(n);
    k_scan3<<<(n + tb - 1) / tb, tb>>>(n, E, nb_scan);
    k_fill<<<(E + tb - 1) / tb, tb>>>(ei, E);

    const float* hin = x;
    for (int l = 0; l < 3; l++) {
        k_gemm_bf16<<<(n + 63) / 64, 256, SMEM_TOT>>>(hin, l, n);
        float* out = (l == 2) ? (float*)d_out : gh;
        k_agg<<<(n * 32 + tb - 1) / tb, tb>>>(bs[l], out, n);
        hin = gh;
    }
}

// round 13
// speedup vs baseline: 1.5866x; 1.0188x over previous
#include <cuda_runtime.h>
#include <cuda_bf16.h>
#include <cstdint>

#define HID 128
#define NMAX 50000
#define EMAX 600000

// smem layout for bf16 GEMM (row stride 136 bf16 = 272 bytes)
#define AST 272
#define SA_BYTES (64 * AST)       // 17408
#define SW_BYTES (128 * AST)      // 34816
#define OFF_ALO SA_BYTES
#define OFF_WHI (2 * SA_BYTES)
#define OFF_WLO (2 * SA_BYTES + SW_BYTES)
#define SMEM_TOT (2 * SA_BYTES + 2 * SW_BYTES)   // 104448 B

// Scratch (static __device__ — no allocations allowed)
__device__ float g_dinv[NMAX];
__device__ float g_hws[(size_t)NMAX * HID];
__device__ float g_h  [(size_t)NMAX * HID];
__device__ int   g_deg[NMAX];
__device__ int   g_rowptr[NMAX + 1];
__device__ int   g_cursor[NMAX];
__device__ int   g_col[EMAX];
__device__ int   g_bsum[128];
__device__ int   g_mode;                               // 1 => int64 edges, 0 => int32
__device__ __nv_bfloat16 g_Wimg[3][2][128 * 136];      // W^T split hi/lo, n-major padded

// ---------------------------------------------------------------------------
__device__ __forceinline__ uint32_t pack_bf16(float lo_elem, float hi_elem) {
    uint32_t r;
    asm("cvt.rn.bf16x2.f32 %0, %1, %2;" : "=r"(r) : "f"(hi_elem), "f"(lo_elem));
    return r;
}
__device__ __forceinline__ void mma16(float* c, const uint32_t* a, const uint32_t b0,
                                      const uint32_t b1) {
    asm volatile(
        "mma.sync.aligned.m16n8k16.row.col.f32.bf16.bf16.f32 "
        "{%0,%1,%2,%3}, {%4,%5,%6,%7}, {%8,%9}, {%0,%1,%2,%3};"
        : "+f"(c[0]), "+f"(c[1]), "+f"(c[2]), "+f"(c[3])
        : "r"(a[0]), "r"(a[1]), "r"(a[2]), "r"(a[3]), "r"(b0), "r"(b1));
}
__device__ __forceinline__ void ldmx4(uint32_t* r, uint32_t addr) {
    asm volatile("ldmatrix.sync.aligned.m8n8.x4.shared.b16 {%0,%1,%2,%3}, [%4];"
                 : "=r"(r[0]), "=r"(r[1]), "=r"(r[2]), "=r"(r[3]) : "r"(addr));
}
__device__ __forceinline__ uint32_t smem_u32(const void* p) {
    uint32_t a;
    asm("{ .reg .u64 t; cvta.to.shared.u64 t, %1; cvt.u32.u64 %0, t; }" : "=r"(a) : "l"(p));
    return a;
}

// ---------------------------------------------------------------------------
// prepB + deg-zero + dtype-detect fused (one launch).
// grid = (67, 3); W split work for idx < 16384; deg zero across whole grid.
__global__ void k_prepB(const float* __restrict__ W0, const float* __restrict__ W1,
                        const float* __restrict__ W2, const void* __restrict__ ei, int n) {
    int gid = (blockIdx.y * 67 + blockIdx.x) * 256 + threadIdx.x;
    if (gid < n) g_deg[gid] = 0;
    if (blockIdx.x == 0 && blockIdx.y == 0 && threadIdx.x < 32) {
        const long long* p = (const long long*)ei;
        int ok = 1;
        for (int k = threadIdx.x; k < 128; k += 32) {
            long long v = p[k];
            if (v < 0 || v >= (long long)n) ok = 0;
        }
        ok = __all_sync(0xffffffffu, ok);
        if (threadIdx.x == 0) g_mode = ok;
    }
    int idx = blockIdx.x * 256 + threadIdx.x;   // k*128 + nn
    if (idx >= 128 * 128) return;
    const float* W = (blockIdx.y == 0) ? W0 : (blockIdx.y == 1) ? W1 : W2;
    int k = idx >> 7, nn = idx & 127;
    float v = W[idx];
    __nv_bfloat16 hi = __float2bfloat16(v);
    __nv_bfloat16 lo = __float2bfloat16(v - __bfloat162float(hi));
    g_Wimg[blockIdx.y][0][nn * 136 + k] = hi;
    g_Wimg[blockIdx.y][1][nn * 136 + k] = lo;
}

__global__ void k_hist(const void* __restrict__ ei, int E) {
    int e = blockIdx.x * blockDim.x + threadIdx.x;
    if (e >= E) return;
    int d;
    if (g_mode) d = (int)((const long long*)ei)[(size_t)E + e];
    else        d = ((const int*)ei)[(size_t)E + e];
    atomicAdd(&g_deg[d], 1);
}
__global__ void k_scan1(int n) {
    __shared__ int s[1024];
    int i = blockIdx.x * 1024 + threadIdx.x;
    int v = (i < n) ? g_deg[i] : 0;
    s[threadIdx.x] = v;
    __syncthreads();
    int acc = v;
    #pragma unroll
    for (int off = 1; off < 1024; off <<= 1) {
        int t = (threadIdx.x >= off) ? s[threadIdx.x - off] : 0;
        __syncthreads();
        acc += t;
        s[threadIdx.x] = acc;
        __syncthreads();
    }
    if (i < n) g_rowptr[i] = acc - v;
    if (threadIdx.x == 1023) g_bsum[blockIdx.x] = acc;
}
__global__ void k_scan3(int n, int E, int nb) {
    __shared__ int s[129];
    if (threadIdx.x == 0) {
        int acc = 0;
        for (int k = 0; k < nb; k++) { s[k] = acc; acc += g_bsum[k]; }
    }
    __syncthreads();
    int i = blockIdx.x * blockDim.x + threadIdx.x;
    if (i < n) {
        int r = g_rowptr[i] + s[i >> 10];
        g_rowptr[i] = r;
        g_cursor[i] = r;
        g_dinv[i] = rsqrtf((float)(g_deg[i] + 1));
    }
    if (i == 0) g_rowptr[n] = E;
}
__global__ void k_fill(const void* __restrict__ ei, int E) {
    int e = blockIdx.x * blockDim.x + threadIdx.x;
    if (e >= E) return;
    int s, d;
    if (g_mode) {
        const long long* p = (const long long*)ei;
        s = (int)p[e]; d = (int)p[(size_t)E + e];
    } else {
        const int* p = (const int*)ei;
        s = p[e]; d = p[(size_t)E + e];
    }
    int pos = atomicAdd(&g_cursor[d], 1);
    g_col[pos] = s;
}

// ---------------------------------------------------------------------------
// Tensor-core GEMM (mma.sync bf16 m16n8k16, 3-term compensated, ldmatrix loads):
// hws = (h @ W) * dinv[row].  Block: 256 thr, M=64 x N=128; warp tile 32x32.
__global__ void __launch_bounds__(256, 2)
k_gemm_bf16(const float* __restrict__ h, int layer, int n) {
    extern __shared__ __align__(16) char sm[];
    char* sA  = sm;
    char* sAl = sm + OFF_ALO;
    char* sW  = sm + OFF_WHI;
    char* sWl = sm + OFF_WLO;
    int tid = threadIdx.x, lane = tid & 31, wid = tid >> 5;
    int row0 = blockIdx.x * 64;

    // stage W (prebuilt split images, linear copy)
    {
        const uint4* wh = (const uint4*)g_Wimg[layer][0];
        const uint4* wl = (const uint4*)g_Wimg[layer][1];
        uint4* dh = (uint4*)sW;
        uint4* dl = (uint4*)sWl;
        for (int i = tid; i < SW_BYTES / 16; i += 256) { dh[i] = wh[i]; dl[i] = wl[i]; }
    }
    // stage A, split hi/lo into bf16
    {
        const float4* h4 = (const float4*)h;
        for (int i = tid; i < 64 * 32; i += 256) {
            int r = i >> 5, c = i & 31;
            int row = row0 + r;
            float4 v = (row < n) ? h4[(size_t)row * 32 + c]
                                 : make_float4(0.f, 0.f, 0.f, 0.f);
            float h0 = __bfloat162float(__float2bfloat16(v.x));
            float h1 = __bfloat162float(__float2bfloat16(v.y));
            float h2 = __bfloat162float(__float2bfloat16(v.z));
            float h3 = __bfloat162float(__float2bfloat16(v.w));
            uint2 hi = make_uint2(pack_bf16(h0, h1), pack_bf16(h2, h3));
            uint2 lo = make_uint2(pack_bf16(v.x - h0, v.y - h1),
                                  pack_bf16(v.z - h2, v.w - h3));
            *(uint2*)(sA  + r * AST + c * 8) = hi;
            *(uint2*)(sAl + r * AST + c * 8) = lo;
        }
    }
    __syncthreads();

    int g = lane >> 2, tg = lane & 3;
    int m0 = (wid >> 2) * 32, n0 = (wid & 3) * 32;

    // ldmatrix lane address pattern: lanes 0-15 -> rows (base + lane&15), k-half 0;
    // lanes 16-31 -> same rows, k-half 1 (+16B).
    int lrow = lane & 15, lhalf = (lane >> 4) * 16;
    uint32_t aAhi0 = smem_u32(sA)  + (m0 + lrow) * AST + lhalf;
    uint32_t aAlo0 = smem_u32(sAl) + (m0 + lrow) * AST + lhalf;
    uint32_t aWhi0 = smem_u32(sW)  + (n0 + lrow) * AST + lhalf;
    uint32_t aWlo0 = smem_u32(sWl) + (n0 + lrow) * AST + lhalf;

    float acc[2][4][4];
    #pragma unroll
    for (int mf = 0; mf < 2; mf++)
        #pragma unroll
        for (int nf = 0; nf < 4; nf++)
            #pragma unroll
            for (int j = 0; j < 4; j++) acc[mf][nf][j] = 0.f;

    #pragma unroll
    for (int ks = 0; ks < 8; ks++) {
        int kb = ks * 32;
        // A fragments: x4 per (mf, hi/lo)
        uint32_t ah[2][4], al[2][4];
        ldmx4(ah[0], aAhi0 + kb);
        ldmx4(ah[1], aAhi0 + 16 * AST + kb);
        ldmx4(al[0], aAlo0 + kb);
        ldmx4(al[1], aAlo0 + 16 * AST + kb);
        // B fragments: x4 covers two nf each -> regs {r0,r2} = nf_even, {r1,r3} = nf_odd
        uint32_t bh[2][4], bl[2][4];
        ldmx4(bh[0], aWhi0 + kb);
        ldmx4(bh[1], aWhi0 + 16 * AST + kb);
        ldmx4(bl[0], aWlo0 + kb);
        ldmx4(bl[1], aWlo0 + 16 * AST + kb);

        #pragma unroll
        for (int np = 0; np < 2; np++) {
            #pragma unroll
            for (int sub = 0; sub < 2; sub++) {
                int nf = np * 2 + sub;
                uint32_t b0 = bh[np][sub], b1 = bh[np][sub + 2];
                mma16(acc[0][nf], ah[0], b0, b1);
                mma16(acc[1][nf], ah[1], b0, b1);
            }
        }
        #pragma unroll
        for (int np = 0; np < 2; np++) {
            #pragma unroll
            for (int sub = 0; sub < 2; sub++) {
                int nf = np * 2 + sub;
                uint32_t b0 = bh[np][sub], b1 = bh[np][sub + 2];
                mma16(acc[0][nf], al[0], b0, b1);
                mma16(acc[1][nf], al[1], b0, b1);
            }
        }
        #pragma unroll
        for (int np = 0; np < 2; np++) {
            #pragma unroll
            for (int sub = 0; sub < 2; sub++) {
                int nf = np * 2 + sub;
                uint32_t b0 = bl[np][sub], b1 = bl[np][sub + 2];
                mma16(acc[0][nf], ah[0], b0, b1);
                mma16(acc[1][nf], ah[1], b0, b1);
            }
        }
    }

    // epilogue: c0,c1 -> (row g, cols tg*2,+1); c2,c3 -> row g+8
    #pragma unroll
    for (int mf = 0; mf < 2; mf++) {
        #pragma unroll
        for (int half = 0; half < 2; half++) {
            int row = row0 + m0 + mf * 16 + g + half * 8;
            if (row < n) {
                float dv = g_dinv[row];
                #pragma unroll
                for (int nf = 0; nf < 4; nf++) {
                    int col = n0 + nf * 8 + tg * 2;
                    float2 o = make_float2(acc[mf][nf][half * 2] * dv,
                                           acc[mf][nf][half * 2 + 1] * dv);
                    *(float2*)&g_hws[(size_t)row * HID + col] = o;
                }
            }
        }
    }
}

// ---------------------------------------------------------------------------
// Gather-aggregate + finalize: one warp per dst node, 4 loads in flight
__global__ void k_agg(const float* __restrict__ b, float* __restrict__ out, int n) {
    int warp = (blockIdx.x * blockDim.x + threadIdx.x) >> 5;
    int lane = threadIdx.x & 31;
    if (warp >= n) return;
    int beg = g_rowptr[warp], end = g_rowptr[warp + 1];

    const float4* hws4 = (const float4*)g_hws;
    float4 sum = hws4[(size_t)warp * 32 + lane];   // self loop

    for (int base = beg; base < end; base += 32) {
        int m = end - base; if (m > 32) m = 32;
        int idx = (lane < m) ? g_col[base + lane] : 0;
        int k = 0;
        for (; k + 4 <= m; k += 4) {
            int s0 = __shfl_sync(0xffffffffu, idx, k);
            int s1 = __shfl_sync(0xffffffffu, idx, k + 1);
            int s2 = __shfl_sync(0xffffffffu, idx, k + 2);
            int s3 = __shfl_sync(0xffffffffu, idx, k + 3);
            float4 v0 = hws4[(size_t)s0 * 32 + lane];
            float4 v1 = hws4[(size_t)s1 * 32 + lane];
            float4 v2 = hws4[(size_t)s2 * 32 + lane];
            float4 v3 = hws4[(size_t)s3 * 32 + lane];
            sum.x += (v0.x + v1.x) + (v2.x + v3.x);
            sum.y += (v0.y + v1.y) + (v2.y + v3.y);
            sum.z += (v0.z + v1.z) + (v2.z + v3.z);
            sum.w += (v0.w + v1.w) + (v2.w + v3.w);
        }
        for (; k < m; k++) {
            int s = __shfl_sync(0xffffffffu, idx, k);
            float4 v = hws4[(size_t)s * 32 + lane];
            sum.x += v.x; sum.y += v.y; sum.z += v.z; sum.w += v.w;
        }
    }

    float dv = g_dinv[warp];
    float4 bb = ((const float4*)b)[lane];
    float4 o;
    o.x = fmaxf(fmaf(sum.x, dv, bb.x), 0.f);
    o.y = fmaxf(fmaf(sum.y, dv, bb.y), 0.f);
    o.z = fmaxf(fmaf(sum.z, dv, bb.z), 0.f);
    o.w = fmaxf(fmaf(sum.w, dv, bb.w), 0.f);
    ((float4*)out)[(size_t)warp * 32 + lane] = o;
}

// ---------------------------------------------------------------------------
extern "C" void kernel_launch(void* const* d_in, const int* in_sizes, int n_in,
                              void* d_out, int out_size) {
    const float* x  = (const float*)d_in[0];
    const void*  ei = d_in[1];
    const float* Ws[3] = {(const float*)d_in[2], (const float*)d_in[4], (const float*)d_in[6]};
    const float* bs[3] = {(const float*)d_in[3], (const float*)d_in[5], (const float*)d_in[7]};
    int n = in_sizes[0] / HID;
    int E = in_sizes[1] / 2;

    cudaFuncSetAttribute(k_gemm_bf16, cudaFuncAttributeMaxDynamicSharedMemorySize, SMEM_TOT);

    float* gh = nullptr;
    cudaGetSymbolAddress((void**)&gh, g_h);

    const int tb = 256;
    int nb_scan = (n + 1023) / 1024;

    k_prepB<<<dim3(67, 3), 256>>>(Ws[0], Ws[1], Ws[2], ei, n);
    k_hist<<<(E + tb - 1) / tb, tb>>>(ei, E);
    k_scan1<<<nb_scan, 1024>>>(n);
    k_scan3<<<(n + tb - 1) / tb, tb>>>(n, E, nb_scan);
    k_fill<<<(E + tb - 1) / tb, tb>>>(ei, E);

    const float* hin = x;
    for (int l = 0; l < 3; l++) {
        k_gemm_bf16<<<(n + 63) / 64, 256, SMEM_TOT>>>(hin, l, n);
        float* out = (l == 2) ? (float*)d_out : gh;
        k_agg<<<(n * 32 + tb - 1) / tb, tb>>>(bs[l], out, n);
        hin = gh;
    }
}

// round 14
// speedup vs baseline: 1.6365x; 1.0315x over previous
#include <cuda_runtime.h>
#include <cuda_bf16.h>
#include <cstdint>

#define HID 128
#define NMAX 50000
#define EMAX 600000

// smem layout for bf16 GEMM (row stride 136 bf16 = 272 bytes)
#define AST 272
#define SA_BYTES (64 * AST)       // 17408
#define SW_BYTES (128 * AST)      // 34816
#define OFF_ALO SA_BYTES
#define OFF_WHI (2 * SA_BYTES)
#define OFF_WLO (2 * SA_BYTES + SW_BYTES)
#define SMEM_TOT (2 * SA_BYTES + 2 * SW_BYTES)   // 104448 B

// Scratch (static __device__ — no allocations allowed)
__device__ float g_dinv[NMAX];
__device__ float g_hws[(size_t)NMAX * HID];
__device__ float g_h  [(size_t)NMAX * HID];
__device__ int   g_deg[NMAX];
__device__ int   g_rowptr[NMAX + 1];
__device__ int   g_cursor[NMAX];
__device__ int   g_col[EMAX];
__device__ int   g_bsum[128];
__device__ int   g_mode;                               // 1 => int64 edges, 0 => int32
__device__ __nv_bfloat16 g_Wimg[3][2][128 * 136];      // W^T split hi/lo, n-major padded

// ---------------------------------------------------------------------------
__device__ __forceinline__ uint32_t pack_bf16(float lo_elem, float hi_elem) {
    uint32_t r;
    asm("cvt.rn.bf16x2.f32 %0, %1, %2;" : "=r"(r) : "f"(hi_elem), "f"(lo_elem));
    return r;
}
__device__ __forceinline__ void mma16(float* c, const uint32_t* a, const uint32_t b0,
                                      const uint32_t b1) {
    asm volatile(
        "mma.sync.aligned.m16n8k16.row.col.f32.bf16.bf16.f32 "
        "{%0,%1,%2,%3}, {%4,%5,%6,%7}, {%8,%9}, {%0,%1,%2,%3};"
        : "+f"(c[0]), "+f"(c[1]), "+f"(c[2]), "+f"(c[3])
        : "r"(a[0]), "r"(a[1]), "r"(a[2]), "r"(a[3]), "r"(b0), "r"(b1));
}
__device__ __forceinline__ void ldmx4(uint32_t* r, uint32_t addr) {
    asm volatile("ldmatrix.sync.aligned.m8n8.x4.shared.b16 {%0,%1,%2,%3}, [%4];"
                 : "=r"(r[0]), "=r"(r[1]), "=r"(r[2]), "=r"(r[3]) : "r"(addr));
}
__device__ __forceinline__ uint32_t smem_u32(const void* p) {
    uint32_t a;
    asm("{ .reg .u64 t; cvta.to.shared.u64 t, %1; cvt.u32.u64 %0, t; }" : "=r"(a) : "l"(p));
    return a;
}

// ---------------------------------------------------------------------------
// prepB + deg-zero + dtype-detect fused (one launch).
__global__ void k_prepB(const float* __restrict__ W0, const float* __restrict__ W1,
                        const float* __restrict__ W2, const void* __restrict__ ei, int n) {
    int gid = (blockIdx.y * 67 + blockIdx.x) * 256 + threadIdx.x;
    if (gid < n) g_deg[gid] = 0;
    if (blockIdx.x == 0 && blockIdx.y == 0 && threadIdx.x < 32) {
        const long long* p = (const long long*)ei;
        int ok = 1;
        for (int k = threadIdx.x; k < 128; k += 32) {
            long long v = p[k];
            if (v < 0 || v >= (long long)n) ok = 0;
        }
        ok = __all_sync(0xffffffffu, ok);
        if (threadIdx.x == 0) g_mode = ok;
    }
    int idx = blockIdx.x * 256 + threadIdx.x;   // k*128 + nn
    if (idx >= 128 * 128) return;
    const float* W = (blockIdx.y == 0) ? W0 : (blockIdx.y == 1) ? W1 : W2;
    int k = idx >> 7, nn = idx & 127;
    float v = W[idx];
    __nv_bfloat16 hi = __float2bfloat16(v);
    __nv_bfloat16 lo = __float2bfloat16(v - __bfloat162float(hi));
    g_Wimg[blockIdx.y][0][nn * 136 + k] = hi;
    g_Wimg[blockIdx.y][1][nn * 136 + k] = lo;
}

__global__ void k_hist(const void* __restrict__ ei, int E) {
    int e = blockIdx.x * blockDim.x + threadIdx.x;
    if (e >= E) return;
    int d;
    if (g_mode) d = (int)((const long long*)ei)[(size_t)E + e];
    else        d = ((const int*)ei)[(size_t)E + e];
    atomicAdd(&g_deg[d], 1);
}
__global__ void k_scan1(int n) {
    __shared__ int s[1024];
    int i = blockIdx.x * 1024 + threadIdx.x;
    int v = (i < n) ? g_deg[i] : 0;
    s[threadIdx.x] = v;
    __syncthreads();
    int acc = v;
    #pragma unroll
    for (int off = 1; off < 1024; off <<= 1) {
        int t = (threadIdx.x >= off) ? s[threadIdx.x - off] : 0;
        __syncthreads();
        acc += t;
        s[threadIdx.x] = acc;
        __syncthreads();
    }
    if (i < n) g_rowptr[i] = acc - v;
    if (threadIdx.x == 1023) g_bsum[blockIdx.x] = acc;
}
__global__ void k_scan3(int n, int E, int nb) {
    __shared__ int s[129];
    if (threadIdx.x == 0) {
        int acc = 0;
        for (int k = 0; k < nb; k++) { s[k] = acc; acc += g_bsum[k]; }
    }
    __syncthreads();
    int i = blockIdx.x * blockDim.x + threadIdx.x;
    if (i < n) {
        int r = g_rowptr[i] + s[i >> 10];
        g_rowptr[i] = r;
        g_cursor[i] = r;
        g_dinv[i] = rsqrtf((float)(g_deg[i] + 1));
    }
    if (i == 0) g_rowptr[n] = E;
}
__global__ void k_fill(const void* __restrict__ ei, int E) {
    int e = blockIdx.x * blockDim.x + threadIdx.x;
    if (e >= E) return;
    int s, d;
    if (g_mode) {
        const long long* p = (const long long*)ei;
        s = (int)p[e]; d = (int)p[(size_t)E + e];
    } else {
        const int* p = (const int*)ei;
        s = p[e]; d = p[(size_t)E + e];
    }
    int pos = atomicAdd(&g_cursor[d], 1);
    g_col[pos] = s;
}

// ---------------------------------------------------------------------------
// Tensor-core GEMM (mma.sync bf16 m16n8k16, 3-term compensated, ldmatrix loads):
// hws = h @ W (UNscaled — dinv is applied in k_agg).
__global__ void __launch_bounds__(256, 2)
k_gemm_bf16(const float* __restrict__ h, int layer, int n) {
    extern __shared__ __align__(16) char sm[];
    char* sA  = sm;
    char* sAl = sm + OFF_ALO;
    char* sW  = sm + OFF_WHI;
    char* sWl = sm + OFF_WLO;
    int tid = threadIdx.x, lane = tid & 31, wid = tid >> 5;
    int row0 = blockIdx.x * 64;

    // stage W (prebuilt split images, linear copy)
    {
        const uint4* wh = (const uint4*)g_Wimg[layer][0];
        const uint4* wl = (const uint4*)g_Wimg[layer][1];
        uint4* dh = (uint4*)sW;
        uint4* dl = (uint4*)sWl;
        for (int i = tid; i < SW_BYTES / 16; i += 256) { dh[i] = wh[i]; dl[i] = wl[i]; }
    }
    // stage A, split hi/lo into bf16
    {
        const float4* h4 = (const float4*)h;
        for (int i = tid; i < 64 * 32; i += 256) {
            int r = i >> 5, c = i & 31;
            int row = row0 + r;
            float4 v = (row < n) ? h4[(size_t)row * 32 + c]
                                 : make_float4(0.f, 0.f, 0.f, 0.f);
            float h0 = __bfloat162float(__float2bfloat16(v.x));
            float h1 = __bfloat162float(__float2bfloat16(v.y));
            float h2 = __bfloat162float(__float2bfloat16(v.z));
            float h3 = __bfloat162float(__float2bfloat16(v.w));
            uint2 hi = make_uint2(pack_bf16(h0, h1), pack_bf16(h2, h3));
            uint2 lo = make_uint2(pack_bf16(v.x - h0, v.y - h1),
                                  pack_bf16(v.z - h2, v.w - h3));
            *(uint2*)(sA  + r * AST + c * 8) = hi;
            *(uint2*)(sAl + r * AST + c * 8) = lo;
        }
    }
    __syncthreads();

    int g = lane >> 2, tg = lane & 3;
    int m0 = (wid >> 2) * 32, n0 = (wid & 3) * 32;

    int lrow = lane & 15, lhalf = (lane >> 4) * 16;
    uint32_t aAhi0 = smem_u32(sA)  + (m0 + lrow) * AST + lhalf;
    uint32_t aAlo0 = smem_u32(sAl) + (m0 + lrow) * AST + lhalf;
    uint32_t aWhi0 = smem_u32(sW)  + (n0 + lrow) * AST + lhalf;
    uint32_t aWlo0 = smem_u32(sWl) + (n0 + lrow) * AST + lhalf;

    float acc[2][4][4];
    #pragma unroll
    for (int mf = 0; mf < 2; mf++)
        #pragma unroll
        for (int nf = 0; nf < 4; nf++)
            #pragma unroll
            for (int j = 0; j < 4; j++) acc[mf][nf][j] = 0.f;

    #pragma unroll
    for (int ks = 0; ks < 8; ks++) {
        int kb = ks * 32;
        uint32_t ah[2][4], al[2][4];
        ldmx4(ah[0], aAhi0 + kb);
        ldmx4(ah[1], aAhi0 + 16 * AST + kb);
        ldmx4(al[0], aAlo0 + kb);
        ldmx4(al[1], aAlo0 + 16 * AST + kb);
        uint32_t bh[2][4], bl[2][4];
        ldmx4(bh[0], aWhi0 + kb);
        ldmx4(bh[1], aWhi0 + 16 * AST + kb);
        ldmx4(bl[0], aWlo0 + kb);
        ldmx4(bl[1], aWlo0 + 16 * AST + kb);

        #pragma unroll
        for (int np = 0; np < 2; np++)
            #pragma unroll
            for (int sub = 0; sub < 2; sub++) {
                int nf = np * 2 + sub;
                uint32_t b0 = bh[np][sub], b1 = bh[np][sub + 2];
                mma16(acc[0][nf], ah[0], b0, b1);
                mma16(acc[1][nf], ah[1], b0, b1);
            }
        #pragma unroll
        for (int np = 0; np < 2; np++)
            #pragma unroll
            for (int sub = 0; sub < 2; sub++) {
                int nf = np * 2 + sub;
                uint32_t b0 = bh[np][sub], b1 = bh[np][sub + 2];
                mma16(acc[0][nf], al[0], b0, b1);
                mma16(acc[1][nf], al[1], b0, b1);
            }
        #pragma unroll
        for (int np = 0; np < 2; np++)
            #pragma unroll
            for (int sub = 0; sub < 2; sub++) {
                int nf = np * 2 + sub;
                uint32_t b0 = bl[np][sub], b1 = bl[np][sub + 2];
                mma16(acc[0][nf], ah[0], b0, b1);
                mma16(acc[1][nf], ah[1], b0, b1);
            }
    }

    #pragma unroll
    for (int mf = 0; mf < 2; mf++)
        #pragma unroll
        for (int half = 0; half < 2; half++) {
            int row = row0 + m0 + mf * 16 + g + half * 8;
            if (row < n) {
                #pragma unroll
                for (int nf = 0; nf < 4; nf++) {
                    int col = n0 + nf * 8 + tg * 2;
                    float2 o = make_float2(acc[mf][nf][half * 2],
                                           acc[mf][nf][half * 2 + 1]);
                    *(float2*)&g_hws[(size_t)row * HID + col] = o;
                }
            }
        }
}

// ---------------------------------------------------------------------------
// Gather-aggregate + finalize: one warp per dst node.
// hws is UNscaled: out[v] = relu( dinv[v]*(hws[v]*dinv[v] + sum_s hws[s]*dinv[s]) + b )
__global__ void k_agg(const float* __restrict__ b, float* __restrict__ out, int n) {
    int warp = (blockIdx.x * blockDim.x + threadIdx.x) >> 5;
    int lane = threadIdx.x & 31;
    if (warp >= n) return;
    int beg = g_rowptr[warp], end = g_rowptr[warp + 1];

    const float4* hws4 = (const float4*)g_hws;
    float dv = g_dinv[warp];
    float4 sv = hws4[(size_t)warp * 32 + lane];    // self loop (x dinv[v])
    float4 sum = make_float4(sv.x * dv, sv.y * dv, sv.z * dv, sv.w * dv);

    for (int base = beg; base < end; base += 32) {
        int m = end - base; if (m > 32) m = 32;
        int idx = (lane < m) ? g_col[base + lane] : 0;
        float dl = (lane < m) ? g_dinv[idx] : 0.f;
        int k = 0;
        for (; k + 4 <= m; k += 4) {
            int s0 = __shfl_sync(0xffffffffu, idx, k);
            int s1 = __shfl_sync(0xffffffffu, idx, k + 1);
            int s2 = __shfl_sync(0xffffffffu, idx, k + 2);
            int s3 = __shfl_sync(0xffffffffu, idx, k + 3);
            float w0 = __shfl_sync(0xffffffffu, dl, k);
            float w1 = __shfl_sync(0xffffffffu, dl, k + 1);
            float w2 = __shfl_sync(0xffffffffu, dl, k + 2);
            float w3 = __shfl_sync(0xffffffffu, dl, k + 3);
            float4 v0 = hws4[(size_t)s0 * 32 + lane];
            float4 v1 = hws4[(size_t)s1 * 32 + lane];
            float4 v2 = hws4[(size_t)s2 * 32 + lane];
            float4 v3 = hws4[(size_t)s3 * 32 + lane];
            sum.x = fmaf(v0.x, w0, fmaf(v1.x, w1, fmaf(v2.x, w2, fmaf(v3.x, w3, sum.x))));
            sum.y = fmaf(v0.y, w0, fmaf(v1.y, w1, fmaf(v2.y, w2, fmaf(v3.y, w3, sum.y))));
            sum.z = fmaf(v0.z, w0, fmaf(v1.z, w1, fmaf(v2.z, w2, fmaf(v3.z, w3, sum.z))));
            sum.w = fmaf(v0.w, w0, fmaf(v1.w, w1, fmaf(v2.w, w2, fmaf(v3.w, w3, sum.w))));
        }
        for (; k < m; k++) {
            int s = __shfl_sync(0xffffffffu, idx, k);
            float w = __shfl_sync(0xffffffffu, dl, k);
            float4 v = hws4[(size_t)s * 32 + lane];
            sum.x = fmaf(v.x, w, sum.x);
            sum.y = fmaf(v.y, w, sum.y);
            sum.z = fmaf(v.z, w, sum.z);
            sum.w = fmaf(v.w, w, sum.w);
        }
    }

    float4 bb = ((const float4*)b)[lane];
    float4 o;
    o.x = fmaxf(fmaf(sum.x, dv, bb.x), 0.f);
    o.y = fmaxf(fmaf(sum.y, dv, bb.y), 0.f);
    o.z = fmaxf(fmaf(sum.z, dv, bb.z), 0.f);
    o.w = fmaxf(fmaf(sum.w, dv, bb.w), 0.f);
    ((float4*)out)[(size_t)warp * 32 + lane] = o;
}

// ---------------------------------------------------------------------------
extern "C" void kernel_launch(void* const* d_in, const int* in_sizes, int n_in,
                              void* d_out, int out_size) {
    const float* x  = (const float*)d_in[0];
    const void*  ei = d_in[1];
    const float* Ws[3] = {(const float*)d_in[2], (const float*)d_in[4], (const float*)d_in[6]};
    const float* bs[3] = {(const float*)d_in[3], (const float*)d_in[5], (const float*)d_in[7]};
    int n = in_sizes[0] / HID;
    int E = in_sizes[1] / 2;

    static cudaStream_t s1 = nullptr;
    static cudaEvent_t evA = nullptr, evB = nullptr;
    if (s1 == nullptr) {
        cudaStreamCreateWithFlags(&s1, cudaStreamNonBlocking);
        cudaEventCreateWithFlags(&evA, cudaEventDisableTiming);
        cudaEventCreateWithFlags(&evB, cudaEventDisableTiming);
    }

    cudaFuncSetAttribute(k_gemm_bf16, cudaFuncAttributeMaxDynamicSharedMemorySize, SMEM_TOT);

    float* gh = nullptr;
    cudaGetSymbolAddress((void**)&gh, g_h);

    const int tb = 256;
    int nb_scan = (n + 1023) / 1024;
    int gemm_blocks = (n + 63) / 64;

    // prepB (W split + deg zero + dtype detect) on main stream
    k_prepB<<<dim3(67, 3), 256>>>(Ws[0], Ws[1], Ws[2], ei, n);

    // fork: layer-0 GEMM (depends only on x + Wimg) runs on s1,
    // CSR build chain runs on the main (capture) stream.
    cudaEventRecord(evA, 0);
    cudaStreamWaitEvent(s1, evA, 0);
    k_gemm_bf16<<<gemm_blocks, 256, SMEM_TOT, s1>>>(x, 0, n);
    cudaEventRecord(evB, s1);

    k_hist<<<(E + tb - 1) / tb, tb>>>(ei, E);
    k_scan1<<<nb_scan, 1024>>>(n);
    k_scan3<<<(n + tb - 1) / tb, tb>>>(n, E, nb_scan);
    k_fill<<<(E + tb - 1) / tb, tb>>>(ei, E);

    // join: agg0 needs both CSR (main) and hws from gemm0 (s1)
    cudaStreamWaitEvent(0, evB, 0);

    k_agg<<<(n * 32 + tb - 1) / tb, tb>>>(bs[0], gh, n);
    for (int l = 1; l < 3; l++) {
        k_gemm_bf16<<<gemm_blocks, 256, SMEM_TOT>>>(gh, l, n);
        float* out = (l == 2) ? (float*)d_out : gh;
        k_agg<<<(n * 32 + tb - 1) / tb, tb>>>(bs[l], out, n);
    }
}